// round 5
// baseline (speedup 1.0000x reference)
#include <cuda_runtime.h>
#include <cstdint>

#define IN_F   4096
#define OUT_F  4096
#define TOKENS 4096

// GEMM tiling: CTA 128(M) x 256(N), warp tile 64x64, BK=32
#define BM 128
#define BN 256
#define BK 32
#define NK (IN_F / BK)        // 128 iterations
#define STAGES 3

// Smem: padded row stride 36 words (conflict-free 32-bit fragment loads)
#define LDS_STRIDE 36
#define A_TILE_B   (BM * LDS_STRIDE * 4)        // 18432 bytes
#define B_TILE_B   (BN * LDS_STRIDE * 4)        // 36864 bytes
#define STAGE_B    (A_TILE_B + B_TILE_B)        // 55296 bytes
#define OFF_BIAS   (STAGES * STAGE_B)           // 165888
#define SMEM_TOTAL (OFF_BIAS + BN * 4)          // 166912

// ---------------------------------------------------------------------------
// Device scratch (alloc-free rule): tf32-rounded X and W, stored as fp32 bits.
// Referenced ONLY from device code (host-shadow trap!).
// ---------------------------------------------------------------------------
__device__ uint32_t g_X[(size_t)TOKENS * IN_F];
__device__ uint32_t g_W[(size_t)OUT_F * IN_F];

// ---------------------------------------------------------------------------
// helpers
// ---------------------------------------------------------------------------
__device__ __forceinline__ uint32_t smem_u32(const void* p) {
    uint32_t a;
    asm("{ .reg .u64 t; cvta.to.shared.u64 t, %1; cvt.u32.u64 %0, t; }"
        : "=r"(a) : "l"(p));
    return a;
}
__device__ __forceinline__ void cp16(uint32_t dst, const void* src) {
    asm volatile("cp.async.cg.shared.global [%0], [%1], 16;" :: "r"(dst), "l"(src));
}
#define CP_COMMIT() asm volatile("cp.async.commit_group;" ::: "memory")
#define CP_WAIT(N)  asm volatile("cp.async.wait_group %0;" :: "n"(N) : "memory")

__device__ __forceinline__ uint32_t f2tf32(float f) {
    uint32_t r;
    asm("cvt.rna.tf32.f32 %0, %1;" : "=r"(r) : "f"(f));
    return r;
}

__device__ __forceinline__ void mma_tf32(float* d, const uint32_t* a, const uint32_t* b) {
    asm volatile(
        "mma.sync.aligned.m16n8k8.row.col.f32.tf32.tf32.f32 "
        "{%0,%1,%2,%3}, {%4,%5,%6,%7}, {%8,%9}, {%0,%1,%2,%3};"
        : "+f"(d[0]), "+f"(d[1]), "+f"(d[2]), "+f"(d[3])
        : "r"(a[0]), "r"(a[1]), "r"(a[2]), "r"(a[3]), "r"(b[0]), "r"(b[1]));
}

// ---------------------------------------------------------------------------
// Pre-pass 1: W = tf32(mu + softplus(rho)*eps)
// ---------------------------------------------------------------------------
__global__ void prep_w_kernel(const float4* __restrict__ mu,
                              const float4* __restrict__ rho,
                              const float4* __restrict__ eps) {
    int i = blockIdx.x * blockDim.x + threadIdx.x;
    float4 m = mu[i], r = rho[i], e = eps[i];
    uint4 o;
    o.x = f2tf32(fmaf(log1pf(__expf(r.x)), e.x, m.x));
    o.y = f2tf32(fmaf(log1pf(__expf(r.y)), e.y, m.y));
    o.z = f2tf32(fmaf(log1pf(__expf(r.z)), e.z, m.z));
    o.w = f2tf32(fmaf(log1pf(__expf(r.w)), e.w, m.w));
    reinterpret_cast<uint4*>(g_W)[i] = o;
}

// Pre-pass 2: X -> tf32
__global__ void prep_x_kernel(const float4* __restrict__ x) {
    int i = blockIdx.x * blockDim.x + threadIdx.x;
    float4 v = x[i];
    uint4 o;
    o.x = f2tf32(v.x);
    o.y = f2tf32(v.y);
    o.z = f2tf32(v.z);
    o.w = f2tf32(v.w);
    reinterpret_cast<uint4*>(g_X)[i] = o;
}

// ---------------------------------------------------------------------------
// tf32 HMMA GEMM: C[T,O] = X @ W^T + bias (bias fused; softplus inline)
// CTA 128x256, BK=32, 3-stage cp.async pipeline.
// 8 warps: warpM = wid&1 (64 rows), warpN = wid>>1 (64 cols).
// Warp tile 64x64 -> 4 m16 x 8 n8 tiles, k in 4 steps of 8.
// LDS/MMA ratio = 1.0 (vs 1.5 for 32x64 tiles).
// ---------------------------------------------------------------------------
__device__ __forceinline__ void load_stage(uint32_t sbase, int stg, int kidx,
                                           int bx, int by, int tid) {
    const uint32_t st = sbase + stg * STAGE_B;
    const int k0 = kidx * BK;
    // A: 128 rows x 32 floats (8 x 16B chunks per row) -> 4 chunks/thread
    #pragma unroll
    for (int it = 0; it < 4; it++) {
        int idx = tid + it * 256;
        int row = idx >> 3, ch = idx & 7;
        cp16(st + row * (LDS_STRIDE * 4) + ch * 16,
             g_X + (size_t)(by * BM + row) * IN_F + k0 + ch * 4);
    }
    // B: 256 rows (out-features) x 32 floats -> 8 chunks/thread
    #pragma unroll
    for (int it = 0; it < 8; it++) {
        int idx = tid + it * 256;
        int row = idx >> 3, ch = idx & 7;
        cp16(st + A_TILE_B + row * (LDS_STRIDE * 4) + ch * 16,
             g_W + (size_t)(bx * BN + row) * IN_F + k0 + ch * 4);
    }
}

__global__ __launch_bounds__(256, 1)
void gemm_tf32_kernel(const float* __restrict__ bmu,
                      const float* __restrict__ brho,
                      const float* __restrict__ beps,
                      float* __restrict__ C) {
    extern __shared__ char smem[];
    const uint32_t sbase = smem_u32(smem);
    const int tid = (int)threadIdx.x;
    const int wid = tid >> 5;
    const int lane = tid & 31;
    const int la = lane >> 2;          // 0..7
    const int lb = lane & 3;           // 0..3
    const int warpM = wid & 1;         // 2 warps along M (64 rows each)
    const int warpN = wid >> 1;        // 4 warps along N (64 cols each)
    const int bx = blockIdx.x;         // N tile
    const int by = blockIdx.y;         // M tile

    // Fused bias into smem: b = mu + softplus(rho)*eps
    float* sb = reinterpret_cast<float*>(smem + OFF_BIAS);
    {
        int col = bx * BN + tid;       // tid covers BN=256
        sb[tid] = fmaf(log1pf(__expf(brho[col])), beps[col], bmu[col]);
    }

    float d[4][8][4];
    #pragma unroll
    for (int mi = 0; mi < 4; mi++)
        #pragma unroll
        for (int ni = 0; ni < 8; ni++)
            #pragma unroll
            for (int j = 0; j < 4; j++) d[mi][ni][j] = 0.0f;

    // Prologue: fill all stages
    #pragma unroll
    for (int s = 0; s < STAGES; s++) {
        load_stage(sbase, s, s, bx, by, tid);
        CP_COMMIT();
    }

    for (int i = 0; i < NK; i++) {
        CP_WAIT(STAGES - 1);
        __syncthreads();

        const int stg = i % STAGES;
        const uint32_t* As = reinterpret_cast<const uint32_t*>(smem + stg * STAGE_B);
        const uint32_t* Bs = reinterpret_cast<const uint32_t*>(smem + stg * STAGE_B + A_TILE_B);

        #pragma unroll
        for (int s = 0; s < 4; s++) {          // k-steps of 8
            const int ck = s * 8 + lb;
            uint32_t a[4][4];
            #pragma unroll
            for (int mi = 0; mi < 4; mi++) {
                const int base = (warpM * 64 + mi * 16 + la) * LDS_STRIDE + ck;
                a[mi][0] = As[base];
                a[mi][1] = As[base + 8 * LDS_STRIDE];
                a[mi][2] = As[base + 4];
                a[mi][3] = As[base + 8 * LDS_STRIDE + 4];
            }
            #pragma unroll
            for (int ni = 0; ni < 8; ni++) {
                const int bbase = (warpN * 64 + ni * 8 + la) * LDS_STRIDE + ck;
                uint32_t b[2];
                b[0] = Bs[bbase];
                b[1] = Bs[bbase + 4];
                #pragma unroll
                for (int mi = 0; mi < 4; mi++)
                    mma_tf32(d[mi][ni], a[mi], b);
            }
        }

        __syncthreads();
        if (i + STAGES < NK)
            load_stage(sbase, stg, i + STAGES, bx, by, tid);
        CP_COMMIT();
    }

    // Epilogue: add bias, write float2 per fragment half
    #pragma unroll
    for (int mi = 0; mi < 4; mi++) {
        const int row0 = by * BM + warpM * 64 + mi * 16 + la;
        #pragma unroll
        for (int ni = 0; ni < 8; ni++) {
            const int cl = warpN * 64 + ni * 8 + 2 * lb;   // local col
            const int col = bx * BN + cl;
            float2 o0, o1;
            o0.x = d[mi][ni][0] + sb[cl];
            o0.y = d[mi][ni][1] + sb[cl + 1];
            o1.x = d[mi][ni][2] + sb[cl];
            o1.y = d[mi][ni][3] + sb[cl + 1];
            *reinterpret_cast<float2*>(C + (size_t)row0 * OUT_F + col)       = o0;
            *reinterpret_cast<float2*>(C + (size_t)(row0 + 8) * OUT_F + col) = o1;
        }
    }
}

// ---------------------------------------------------------------------------
// Inputs (metadata order):
//   0: x [T,I]  1: weight_mu [O,I]  2: weight_rho [O,I]
//   3: bias_mu [O]  4: bias_rho [O]  5: weight_eps [O,I]  6: bias_eps [O]
// ---------------------------------------------------------------------------
extern "C" void kernel_launch(void* const* d_in, const int* in_sizes, int n_in,
                              void* d_out, int out_size) {
    const float* x    = (const float*)d_in[0];
    const float* wmu  = (const float*)d_in[1];
    const float* wrho = (const float*)d_in[2];
    const float* bmu  = (const float*)d_in[3];
    const float* brho = (const float*)d_in[4];
    const float* weps = (const float*)d_in[5];
    const float* beps = (const float*)d_in[6];
    float* out = (float*)d_out;

    {
        int total4 = (OUT_F * IN_F) / 4;
        prep_w_kernel<<<total4 / 256, 256>>>(
            (const float4*)wmu, (const float4*)wrho, (const float4*)weps);
        prep_x_kernel<<<(TOKENS * IN_F / 4) / 256, 256>>>((const float4*)x);
    }

    cudaFuncSetAttribute(gemm_tf32_kernel,
                         cudaFuncAttributeMaxDynamicSharedMemorySize, SMEM_TOTAL);
    dim3 grid(OUT_F / BN, TOKENS / BM);   // (16, 32)
    gemm_tf32_kernel<<<grid, 256, SMEM_TOTAL>>>(bmu, brho, beps, out);
}

// round 9
// speedup vs baseline: 1.1094x; 1.1094x over previous
#include <cuda_runtime.h>
#include <cstdint>

#define IN_F   4096
#define OUT_F  4096
#define TOKENS 4096

// GEMM tiling: CTA 128x128, 4 warps, warp tile 64x64, BK=32
#define BM 128
#define BN 128
#define BK 32
#define NK (IN_F / BK)        // 128 iterations
#define STAGES 3
#define NTHREADS 128

// Smem: padded row stride 36 words (conflict-free 32-bit fragment loads)
#define LDS_STRIDE 36
#define A_TILE_B   (BM * LDS_STRIDE * 4)        // 18432 bytes
#define B_TILE_B   (BN * LDS_STRIDE * 4)        // 18432 bytes
#define STAGE_B    (A_TILE_B + B_TILE_B)        // 36864 bytes
#define OFF_BIAS   (STAGES * STAGE_B)           // 110592
#define SMEM_TOTAL (OFF_BIAS + BN * 4)          // 111104 -> 2 CTAs/SM

// ---------------------------------------------------------------------------
// Device scratch (alloc-free rule): tf32-rounded X and W, stored as fp32 bits.
// Referenced ONLY from device code (host-shadow trap!).
// ---------------------------------------------------------------------------
__device__ uint32_t g_X[(size_t)TOKENS * IN_F];
__device__ uint32_t g_W[(size_t)OUT_F * IN_F];

// ---------------------------------------------------------------------------
// helpers
// ---------------------------------------------------------------------------
__device__ __forceinline__ uint32_t smem_u32(const void* p) {
    uint32_t a;
    asm("{ .reg .u64 t; cvta.to.shared.u64 t, %1; cvt.u32.u64 %0, t; }"
        : "=r"(a) : "l"(p));
    return a;
}
__device__ __forceinline__ void cp16(uint32_t dst, const void* src) {
    asm volatile("cp.async.cg.shared.global [%0], [%1], 16;" :: "r"(dst), "l"(src));
}
#define CP_COMMIT() asm volatile("cp.async.commit_group;" ::: "memory")
#define CP_WAIT(N)  asm volatile("cp.async.wait_group %0;" :: "n"(N) : "memory")

__device__ __forceinline__ uint32_t f2tf32(float f) {
    uint32_t r;
    asm("cvt.rna.tf32.f32 %0, %1;" : "=r"(r) : "f"(f));
    return r;
}

__device__ __forceinline__ void mma_tf32(float* d, const uint32_t* a, const uint32_t* b) {
    asm volatile(
        "mma.sync.aligned.m16n8k8.row.col.f32.tf32.tf32.f32 "
        "{%0,%1,%2,%3}, {%4,%5,%6,%7}, {%8,%9}, {%0,%1,%2,%3};"
        : "+f"(d[0]), "+f"(d[1]), "+f"(d[2]), "+f"(d[3])
        : "r"(a[0]), "r"(a[1]), "r"(a[2]), "r"(a[3]), "r"(b[0]), "r"(b[1]));
}

// ---------------------------------------------------------------------------
// Pre-pass 1: W = tf32(mu + softplus(rho)*eps)
// ---------------------------------------------------------------------------
__global__ void prep_w_kernel(const float4* __restrict__ mu,
                              const float4* __restrict__ rho,
                              const float4* __restrict__ eps) {
    int i = blockIdx.x * blockDim.x + threadIdx.x;
    float4 m = mu[i], r = rho[i], e = eps[i];
    uint4 o;
    o.x = f2tf32(fmaf(log1pf(__expf(r.x)), e.x, m.x));
    o.y = f2tf32(fmaf(log1pf(__expf(r.y)), e.y, m.y));
    o.z = f2tf32(fmaf(log1pf(__expf(r.z)), e.z, m.z));
    o.w = f2tf32(fmaf(log1pf(__expf(r.w)), e.w, m.w));
    reinterpret_cast<uint4*>(g_W)[i] = o;
}

// Pre-pass 2: X -> tf32
__global__ void prep_x_kernel(const float4* __restrict__ x) {
    int i = blockIdx.x * blockDim.x + threadIdx.x;
    float4 v = x[i];
    uint4 o;
    o.x = f2tf32(v.x);
    o.y = f2tf32(v.y);
    o.z = f2tf32(v.z);
    o.w = f2tf32(v.w);
    reinterpret_cast<uint4*>(g_X)[i] = o;
}

// ---------------------------------------------------------------------------
// tf32 HMMA GEMM: C[T,O] = X @ W^T + bias (bias fused; softplus inline)
// CTA 128x128, 4 warps (2x2 grid of 64x64 warp tiles), BK=32, 3-stage
// cp.async pipeline.
//
// ORDER MATTERS (memory model): cp.async wait_group is PER-THREAD. The only
// correct one-sync pattern is WAIT -> SYNCTHREADS -> (issue next load) ->
// COMPUTE. The sync after the wait is what publishes *other* threads'
// completed copies; putting the sync before the wait (R6/R7) is a race.
// ---------------------------------------------------------------------------
__device__ __forceinline__ void load_stage(uint32_t sbase, int stg, int kidx,
                                           int bx, int by, int tid) {
    const uint32_t st = sbase + stg * STAGE_B;
    const int k0 = kidx * BK;
    // A: 128 rows x 32 floats = 1024 x 16B chunks -> 8 per thread
    #pragma unroll
    for (int it = 0; it < 8; it++) {
        int idx = tid + it * NTHREADS;
        int row = idx >> 3, ch = idx & 7;
        cp16(st + row * (LDS_STRIDE * 4) + ch * 16,
             g_X + (size_t)(by * BM + row) * IN_F + k0 + ch * 4);
    }
    // B: 128 rows (out-features) x 32 floats -> 8 per thread
    #pragma unroll
    for (int it = 0; it < 8; it++) {
        int idx = tid + it * NTHREADS;
        int row = idx >> 3, ch = idx & 7;
        cp16(st + A_TILE_B + row * (LDS_STRIDE * 4) + ch * 16,
             g_W + (size_t)(bx * BN + row) * IN_F + k0 + ch * 4);
    }
}

__global__ __launch_bounds__(NTHREADS, 2)
void gemm_tf32_kernel(const float* __restrict__ bmu,
                      const float* __restrict__ brho,
                      const float* __restrict__ beps,
                      float* __restrict__ C) {
    extern __shared__ char smem[];
    const uint32_t sbase = smem_u32(smem);
    const int tid = (int)threadIdx.x;
    const int wid = tid >> 5;          // 0..3
    const int lane = tid & 31;
    const int la = lane >> 2;          // 0..7
    const int lb = lane & 3;           // 0..3
    const int warpM = wid & 1;         // 2 warps along M (64 rows each)
    const int warpN = wid >> 1;        // 2 warps along N (64 cols each)
    const int bx = blockIdx.x;         // N tile
    const int by = blockIdx.y;         // M tile

    // Fused bias into smem: b = mu + softplus(rho)*eps (tid covers BN=128)
    float* sb = reinterpret_cast<float*>(smem + OFF_BIAS);
    {
        int col = bx * BN + tid;
        sb[tid] = fmaf(log1pf(__expf(brho[col])), beps[col], bmu[col]);
    }

    float d[4][8][4];
    #pragma unroll
    for (int mi = 0; mi < 4; mi++)
        #pragma unroll
        for (int ni = 0; ni < 8; ni++)
            #pragma unroll
            for (int j = 0; j < 4; j++) d[mi][ni][j] = 0.0f;

    // Prologue: preload groups 0,1 into stages 0,1
    load_stage(sbase, 0, 0, bx, by, tid);
    CP_COMMIT();
    load_stage(sbase, 1, 1, bx, by, tid);
    CP_COMMIT();

    for (int i = 0; i < NK; i++) {
        // 1) Retire group i (own copies). Pending at top: {i, i+1} except
        //    the last iteration where only {NK-1} remains -> full drain.
        if (i < NK - 1) { CP_WAIT(1); } else { CP_WAIT(0); }
        // 2) Publish ALL threads' completed copies + bound warp skew.
        //    Also guarantees all warps finished compute(i-1), so writing
        //    stage (i+2)%3 == (i-1)%3 below is WAR-safe.
        __syncthreads();
        // 3) Issue next load early (max prefetch distance), commit group i+2.
        if (i + 2 < NK) {
            load_stage(sbase, (i + 2) % STAGES, i + 2, bx, by, tid);
            CP_COMMIT();
        }

        // 4) Compute on stage i%3.
        const int stg = i % STAGES;
        const uint32_t* As = reinterpret_cast<const uint32_t*>(smem + stg * STAGE_B);
        const uint32_t* Bs = reinterpret_cast<const uint32_t*>(smem + stg * STAGE_B + A_TILE_B);

        #pragma unroll
        for (int s = 0; s < 4; s++) {          // k-steps of 8
            const int ck = s * 8 + lb;
            uint32_t a[4][4];
            #pragma unroll
            for (int mi = 0; mi < 4; mi++) {
                const int base = (warpM * 64 + mi * 16 + la) * LDS_STRIDE + ck;
                a[mi][0] = As[base];
                a[mi][1] = As[base + 8 * LDS_STRIDE];
                a[mi][2] = As[base + 4];
                a[mi][3] = As[base + 8 * LDS_STRIDE + 4];
            }
            #pragma unroll
            for (int ni = 0; ni < 8; ni++) {
                const int bbase = (warpN * 64 + ni * 8 + la) * LDS_STRIDE + ck;
                uint32_t b[2];
                b[0] = Bs[bbase];
                b[1] = Bs[bbase + 4];
                #pragma unroll
                for (int mi = 0; mi < 4; mi++)
                    mma_tf32(d[mi][ni], a[mi], b);
            }
        }
    }

    // Epilogue: add bias, write float2 per fragment half
    #pragma unroll
    for (int mi = 0; mi < 4; mi++) {
        const int row0 = by * BM + warpM * 64 + mi * 16 + la;
        #pragma unroll
        for (int ni = 0; ni < 8; ni++) {
            const int cl = warpN * 64 + ni * 8 + 2 * lb;   // local col
            const int col = bx * BN + cl;
            float2 o0, o1;
            o0.x = d[mi][ni][0] + sb[cl];
            o0.y = d[mi][ni][1] + sb[cl + 1];
            o1.x = d[mi][ni][2] + sb[cl];
            o1.y = d[mi][ni][3] + sb[cl + 1];
            *reinterpret_cast<float2*>(C + (size_t)row0 * OUT_F + col)       = o0;
            *reinterpret_cast<float2*>(C + (size_t)(row0 + 8) * OUT_F + col) = o1;
        }
    }
}

// ---------------------------------------------------------------------------
// Inputs (metadata order):
//   0: x [T,I]  1: weight_mu [O,I]  2: weight_rho [O,I]
//   3: bias_mu [O]  4: bias_rho [O]  5: weight_eps [O,I]  6: bias_eps [O]
// ---------------------------------------------------------------------------
extern "C" void kernel_launch(void* const* d_in, const int* in_sizes, int n_in,
                              void* d_out, int out_size) {
    const float* x    = (const float*)d_in[0];
    const float* wmu  = (const float*)d_in[1];
    const float* wrho = (const float*)d_in[2];
    const float* bmu  = (const float*)d_in[3];
    const float* brho = (const float*)d_in[4];
    const float* weps = (const float*)d_in[5];
    const float* beps = (const float*)d_in[6];
    float* out = (float*)d_out;

    {
        int total4 = (OUT_F * IN_F) / 4;
        prep_w_kernel<<<total4 / 256, 256>>>(
            (const float4*)wmu, (const float4*)wrho, (const float4*)weps);
        prep_x_kernel<<<(TOKENS * IN_F / 4) / 256, 256>>>((const float4*)x);
    }

    cudaFuncSetAttribute(gemm_tf32_kernel,
                         cudaFuncAttributeMaxDynamicSharedMemorySize, SMEM_TOTAL);
    dim3 grid(OUT_F / BN, TOKENS / BM);   // (32, 32)
    gemm_tf32_kernel<<<grid, NTHREADS, SMEM_TOTAL>>>(bmu, brho, beps, out);
}

// round 10
// speedup vs baseline: 1.1101x; 1.0006x over previous
#include <cuda_runtime.h>
#include <cstdint>

#define IN_F   4096
#define OUT_F  4096
#define TOKENS 4096

// GEMM tiling: CTA 128x128, 4 warps, warp tile 64x64, BK=32
#define BM 128
#define BN 128
#define BK 32
#define NK (IN_F / BK)        // 128 iterations
#define STAGES 3
#define NTHREADS 128

// Smem: padded row stride 36 words (conflict-free 32-bit fragment loads)
#define LDS_STRIDE 36
#define A_TILE_B   (BM * LDS_STRIDE * 4)        // 18432 bytes
#define B_TILE_B   (BN * LDS_STRIDE * 4)        // 18432 bytes
#define STAGE_B    (A_TILE_B + B_TILE_B)        // 36864 bytes
#define OFF_BIAS   (STAGES * STAGE_B)           // 110592
#define SMEM_TOTAL (OFF_BIAS + BN * 4)          // 111104 -> 2 CTAs/SM

// ---------------------------------------------------------------------------
// Device scratch (alloc-free rule): tf32-rounded X and W, stored as fp32 bits.
// Referenced ONLY from device code (host-shadow trap!).
// ---------------------------------------------------------------------------
__device__ uint32_t g_X[(size_t)TOKENS * IN_F];
__device__ uint32_t g_W[(size_t)OUT_F * IN_F];

// ---------------------------------------------------------------------------
// helpers
// ---------------------------------------------------------------------------
__device__ __forceinline__ uint32_t smem_u32(const void* p) {
    uint32_t a;
    asm("{ .reg .u64 t; cvta.to.shared.u64 t, %1; cvt.u32.u64 %0, t; }"
        : "=r"(a) : "l"(p));
    return a;
}
__device__ __forceinline__ void cp16(uint32_t dst, const void* src) {
    asm volatile("cp.async.cg.shared.global [%0], [%1], 16;" :: "r"(dst), "l"(src));
}
#define CP_COMMIT() asm volatile("cp.async.commit_group;" ::: "memory")
#define CP_WAIT(N)  asm volatile("cp.async.wait_group %0;" :: "n"(N) : "memory")

__device__ __forceinline__ uint32_t f2tf32(float f) {
    uint32_t r;
    asm("cvt.rna.tf32.f32 %0, %1;" : "=r"(r) : "f"(f));
    return r;
}

__device__ __forceinline__ void mma_tf32(float* d, const uint32_t* a, const uint32_t* b) {
    asm volatile(
        "mma.sync.aligned.m16n8k8.row.col.f32.tf32.tf32.f32 "
        "{%0,%1,%2,%3}, {%4,%5,%6,%7}, {%8,%9}, {%0,%1,%2,%3};"
        : "+f"(d[0]), "+f"(d[1]), "+f"(d[2]), "+f"(d[3])
        : "r"(a[0]), "r"(a[1]), "r"(a[2]), "r"(a[3]), "r"(b[0]), "r"(b[1]));
}

// ---------------------------------------------------------------------------
// Pre-pass 1: W = tf32(mu + softplus(rho)*eps)
// ---------------------------------------------------------------------------
__global__ void prep_w_kernel(const float4* __restrict__ mu,
                              const float4* __restrict__ rho,
                              const float4* __restrict__ eps) {
    int i = blockIdx.x * blockDim.x + threadIdx.x;
    float4 m = mu[i], r = rho[i], e = eps[i];
    uint4 o;
    o.x = f2tf32(fmaf(log1pf(__expf(r.x)), e.x, m.x));
    o.y = f2tf32(fmaf(log1pf(__expf(r.y)), e.y, m.y));
    o.z = f2tf32(fmaf(log1pf(__expf(r.z)), e.z, m.z));
    o.w = f2tf32(fmaf(log1pf(__expf(r.w)), e.w, m.w));
    reinterpret_cast<uint4*>(g_W)[i] = o;
}

// Pre-pass 2: X -> tf32
__global__ void prep_x_kernel(const float4* __restrict__ x) {
    int i = blockIdx.x * blockDim.x + threadIdx.x;
    float4 v = x[i];
    uint4 o;
    o.x = f2tf32(v.x);
    o.y = f2tf32(v.y);
    o.z = f2tf32(v.z);
    o.w = f2tf32(v.w);
    reinterpret_cast<uint4*>(g_X)[i] = o;
}

// ---------------------------------------------------------------------------
// tf32 HMMA GEMM: C[T,O] = X @ W^T + bias (bias fused; softplus inline)
// CTA 128x128, 4 warps (2x2 grid of 64x64 warp tiles), BK=32, 3-stage
// cp.async pipeline, WAIT -> SYNC -> issue -> compute ordering (per-thread
// wait_group semantics; sync publishes other threads' copies).
//
// NEW (R10): register double-buffered fragments — k-step s+1's LDS issue
// overlaps k-step s's 32 MMAs, hiding the 29-cyc LDS latency that was the
// dominant exposed stall.
// ---------------------------------------------------------------------------
__device__ __forceinline__ void load_stage(uint32_t sbase, int stg, int kidx,
                                           int bx, int by, int tid) {
    const uint32_t st = sbase + stg * STAGE_B;
    const int k0 = kidx * BK;
    // A: 128 rows x 32 floats = 1024 x 16B chunks -> 8 per thread
    #pragma unroll
    for (int it = 0; it < 8; it++) {
        int idx = tid + it * NTHREADS;
        int row = idx >> 3, ch = idx & 7;
        cp16(st + row * (LDS_STRIDE * 4) + ch * 16,
             g_X + (size_t)(by * BM + row) * IN_F + k0 + ch * 4);
    }
    // B: 128 rows (out-features) x 32 floats -> 8 per thread
    #pragma unroll
    for (int it = 0; it < 8; it++) {
        int idx = tid + it * NTHREADS;
        int row = idx >> 3, ch = idx & 7;
        cp16(st + A_TILE_B + row * (LDS_STRIDE * 4) + ch * 16,
             g_W + (size_t)(bx * BN + row) * IN_F + k0 + ch * 4);
    }
}

__global__ __launch_bounds__(NTHREADS, 2)
void gemm_tf32_kernel(const float* __restrict__ bmu,
                      const float* __restrict__ brho,
                      const float* __restrict__ beps,
                      float* __restrict__ C) {
    extern __shared__ char smem[];
    const uint32_t sbase = smem_u32(smem);
    const int tid = (int)threadIdx.x;
    const int wid = tid >> 5;          // 0..3
    const int lane = tid & 31;
    const int la = lane >> 2;          // 0..7
    const int lb = lane & 3;           // 0..3
    const int warpM = wid & 1;         // 2 warps along M (64 rows each)
    const int warpN = wid >> 1;        // 2 warps along N (64 cols each)
    const int bx = blockIdx.x;         // N tile
    const int by = blockIdx.y;         // M tile

    // Fused bias into smem: b = mu + softplus(rho)*eps (tid covers BN=128)
    float* sb = reinterpret_cast<float*>(smem + OFF_BIAS);
    {
        int col = bx * BN + tid;
        sb[tid] = fmaf(log1pf(__expf(brho[col])), beps[col], bmu[col]);
    }

    float d[4][8][4];
    #pragma unroll
    for (int mi = 0; mi < 4; mi++)
        #pragma unroll
        for (int ni = 0; ni < 8; ni++)
            #pragma unroll
            for (int j = 0; j < 4; j++) d[mi][ni][j] = 0.0f;

    // Prologue: preload groups 0,1 into stages 0,1
    load_stage(sbase, 0, 0, bx, by, tid);
    CP_COMMIT();
    load_stage(sbase, 1, 1, bx, by, tid);
    CP_COMMIT();

    // Fragment base offsets (element indices into padded smem tiles)
    const int aoff = (warpM * 64 + la) * LDS_STRIDE;   // + mi*16*36 + ck
    const int boff = (warpN * 64 + la) * LDS_STRIDE;   // + ni*8*36 + ck

    for (int i = 0; i < NK; i++) {
        // 1) Retire group i (own copies); last iter: full drain.
        if (i < NK - 1) { CP_WAIT(1); } else { CP_WAIT(0); }
        // 2) Publish all threads' copies; WAR-protect stage (i+2)%3.
        __syncthreads();
        // 3) Issue next stage load early.
        if (i + 2 < NK) {
            load_stage(sbase, (i + 2) % STAGES, i + 2, bx, by, tid);
            CP_COMMIT();
        }

        // 4) Compute on stage i%3 with double-buffered fragments.
        const int stg = i % STAGES;
        const uint32_t* As = reinterpret_cast<const uint32_t*>(smem + stg * STAGE_B);
        const uint32_t* Bs = reinterpret_cast<const uint32_t*>(smem + stg * STAGE_B + A_TILE_B);

        uint32_t a[2][4][4], b[2][8][2];

        // Preload k-step 0 fragments
        {
            const int ck = lb;
            #pragma unroll
            for (int mi = 0; mi < 4; mi++) {
                const int base = aoff + mi * (16 * LDS_STRIDE) + ck;
                a[0][mi][0] = As[base];
                a[0][mi][1] = As[base + 8 * LDS_STRIDE];
                a[0][mi][2] = As[base + 4];
                a[0][mi][3] = As[base + 8 * LDS_STRIDE + 4];
            }
            #pragma unroll
            for (int ni = 0; ni < 8; ni++) {
                const int base = boff + ni * (8 * LDS_STRIDE) + ck;
                b[0][ni][0] = Bs[base];
                b[0][ni][1] = Bs[base + 4];
            }
        }

        #pragma unroll
        for (int s = 0; s < 4; s++) {          // k-steps of 8
            const int cur = s & 1;
            const int nxt = cur ^ 1;
            if (s < 3) {
                // Prefetch next k-step's fragments; these LDS issue before
                // the MMAs below and complete under them.
                const int ck = (s + 1) * 8 + lb;
                #pragma unroll
                for (int mi = 0; mi < 4; mi++) {
                    const int base = aoff + mi * (16 * LDS_STRIDE) + ck;
                    a[nxt][mi][0] = As[base];
                    a[nxt][mi][1] = As[base + 8 * LDS_STRIDE];
                    a[nxt][mi][2] = As[base + 4];
                    a[nxt][mi][3] = As[base + 8 * LDS_STRIDE + 4];
                }
                #pragma unroll
                for (int ni = 0; ni < 8; ni++) {
                    const int base = boff + ni * (8 * LDS_STRIDE) + ck;
                    b[nxt][ni][0] = Bs[base];
                    b[nxt][ni][1] = Bs[base + 4];
                }
            }
            #pragma unroll
            for (int ni = 0; ni < 8; ni++)
                #pragma unroll
                for (int mi = 0; mi < 4; mi++)
                    mma_tf32(d[mi][ni], a[cur][mi], b[cur][ni]);
        }
    }

    // Epilogue: add bias, write float2 per fragment half
    #pragma unroll
    for (int mi = 0; mi < 4; mi++) {
        const int row0 = by * BM + warpM * 64 + mi * 16 + la;
        #pragma unroll
        for (int ni = 0; ni < 8; ni++) {
            const int cl = warpN * 64 + ni * 8 + 2 * lb;   // local col
            const int col = bx * BN + cl;
            float2 o0, o1;
            o0.x = d[mi][ni][0] + sb[cl];
            o0.y = d[mi][ni][1] + sb[cl + 1];
            o1.x = d[mi][ni][2] + sb[cl];
            o1.y = d[mi][ni][3] + sb[cl + 1];
            *reinterpret_cast<float2*>(C + (size_t)row0 * OUT_F + col)       = o0;
            *reinterpret_cast<float2*>(C + (size_t)(row0 + 8) * OUT_F + col) = o1;
        }
    }
}

// ---------------------------------------------------------------------------
// Inputs (metadata order):
//   0: x [T,I]  1: weight_mu [O,I]  2: weight_rho [O,I]
//   3: bias_mu [O]  4: bias_rho [O]  5: weight_eps [O,I]  6: bias_eps [O]
// ---------------------------------------------------------------------------
extern "C" void kernel_launch(void* const* d_in, const int* in_sizes, int n_in,
                              void* d_out, int out_size) {
    const float* x    = (const float*)d_in[0];
    const float* wmu  = (const float*)d_in[1];
    const float* wrho = (const float*)d_in[2];
    const float* bmu  = (const float*)d_in[3];
    const float* brho = (const float*)d_in[4];
    const float* weps = (const float*)d_in[5];
    const float* beps = (const float*)d_in[6];
    float* out = (float*)d_out;

    {
        int total4 = (OUT_F * IN_F) / 4;
        prep_w_kernel<<<total4 / 256, 256>>>(
            (const float4*)wmu, (const float4*)wrho, (const float4*)weps);
        prep_x_kernel<<<(TOKENS * IN_F / 4) / 256, 256>>>((const float4*)x);
    }

    cudaFuncSetAttribute(gemm_tf32_kernel,
                         cudaFuncAttributeMaxDynamicSharedMemorySize, SMEM_TOTAL);
    dim3 grid(OUT_F / BN, TOKENS / BM);   // (32, 32)
    gemm_tf32_kernel<<<grid, NTHREADS, SMEM_TOTAL>>>(bmu, brho, beps, out);
}

// round 11
// speedup vs baseline: 2.0694x; 1.8642x over previous
#include <cuda_runtime.h>
#include <cuda_fp16.h>
#include <cstdint>

#define IN_F   4096
#define OUT_F  4096
#define TOKENS 4096

// GEMM tiling: CTA 128x128, 4 warps, warp tile 64x64, BK=64 (fp16 halves)
#define BM 128
#define BN 128
#define BK 64
#define NK (IN_F / BK)        // 64 iterations
#define STAGES 3
#define NTHREADS 128

// Smem: rows of 64 halves = 32 data words, padded to 36 words (144B).
// Stride 36 words: banks = 4*row + col (mod 32) -> conflict-free frag loads.
#define LDS_STRIDE 36
#define A_TILE_B   (BM * LDS_STRIDE * 4)        // 18432 bytes
#define B_TILE_B   (BN * LDS_STRIDE * 4)        // 18432 bytes
#define STAGE_B    (A_TILE_B + B_TILE_B)        // 36864 bytes
#define OFF_BIAS   (STAGES * STAGE_B)           // 110592
#define SMEM_TOTAL (OFF_BIAS + BN * 4)          // 111104 -> 2 CTAs/SM

// ---------------------------------------------------------------------------
// Device scratch (alloc-free rule): fp16 X and W.
// Referenced ONLY from device code (host-shadow trap!).
// ---------------------------------------------------------------------------
__device__ __half g_X[(size_t)TOKENS * IN_F];
__device__ __half g_W[(size_t)OUT_F * IN_F];

// ---------------------------------------------------------------------------
// helpers
// ---------------------------------------------------------------------------
__device__ __forceinline__ uint32_t smem_u32(const void* p) {
    uint32_t a;
    asm("{ .reg .u64 t; cvta.to.shared.u64 t, %1; cvt.u32.u64 %0, t; }"
        : "=r"(a) : "l"(p));
    return a;
}
__device__ __forceinline__ void cp16(uint32_t dst, const void* src) {
    asm volatile("cp.async.cg.shared.global [%0], [%1], 16;" :: "r"(dst), "l"(src));
}
#define CP_COMMIT() asm volatile("cp.async.commit_group;" ::: "memory")
#define CP_WAIT(N)  asm volatile("cp.async.wait_group %0;" :: "n"(N) : "memory")

// fp16 HMMA: m16n8k16, fp32 accumulate. 2048 MACs/instr (2x tf32 k8).
__device__ __forceinline__ void mma_f16(float* d, const uint32_t* a, const uint32_t* b) {
    asm volatile(
        "mma.sync.aligned.m16n8k16.row.col.f32.f16.f16.f32 "
        "{%0,%1,%2,%3}, {%4,%5,%6,%7}, {%8,%9}, {%0,%1,%2,%3};"
        : "+f"(d[0]), "+f"(d[1]), "+f"(d[2]), "+f"(d[3])
        : "r"(a[0]), "r"(a[1]), "r"(a[2]), "r"(a[3]), "r"(b[0]), "r"(b[1]));
}

// ---------------------------------------------------------------------------
// Pre-pass 1: W = fp16(mu + softplus(rho)*eps)   (fp16 mantissa == tf32's)
// ---------------------------------------------------------------------------
__global__ void prep_w_kernel(const float4* __restrict__ mu,
                              const float4* __restrict__ rho,
                              const float4* __restrict__ eps) {
    int i = blockIdx.x * blockDim.x + threadIdx.x;
    float4 m = mu[i], r = rho[i], e = eps[i];
    float w0 = fmaf(log1pf(__expf(r.x)), e.x, m.x);
    float w1 = fmaf(log1pf(__expf(r.y)), e.y, m.y);
    float w2 = fmaf(log1pf(__expf(r.z)), e.z, m.z);
    float w3 = fmaf(log1pf(__expf(r.w)), e.w, m.w);
    __half2 p0 = __floats2half2_rn(w0, w1);
    __half2 p1 = __floats2half2_rn(w2, w3);
    uint2 o;
    o.x = *reinterpret_cast<uint32_t*>(&p0);
    o.y = *reinterpret_cast<uint32_t*>(&p1);
    reinterpret_cast<uint2*>(g_W)[i] = o;
}

// Pre-pass 2: X -> fp16
__global__ void prep_x_kernel(const float4* __restrict__ x) {
    int i = blockIdx.x * blockDim.x + threadIdx.x;
    float4 v = x[i];
    __half2 p0 = __floats2half2_rn(v.x, v.y);
    __half2 p1 = __floats2half2_rn(v.z, v.w);
    uint2 o;
    o.x = *reinterpret_cast<uint32_t*>(&p0);
    o.y = *reinterpret_cast<uint32_t*>(&p1);
    reinterpret_cast<uint2*>(g_X)[i] = o;
}

// ---------------------------------------------------------------------------
// fp16 HMMA GEMM: C[T,O] = X @ W^T + bias (bias fused; softplus inline)
// CTA 128x128, 4 warps (2x2 grid of 64x64 warp tiles), BK=64 halves,
// 3-stage cp.async pipeline, WAIT -> SYNC -> issue -> compute ordering
// (cp.async wait_group is per-thread; the sync publishes other threads'
// copies — proven correct in R9).
// ---------------------------------------------------------------------------
__device__ __forceinline__ void load_stage(uint32_t sbase, int stg, int kidx,
                                           int bx, int by, int tid) {
    const uint32_t st = sbase + stg * STAGE_B;
    const int k0 = kidx * BK;           // in halves
    // A: 128 rows x 64 halves (8 x 16B chunks per row) -> 8 per thread
    #pragma unroll
    for (int it = 0; it < 8; it++) {
        int idx = tid + it * NTHREADS;
        int row = idx >> 3, ch = idx & 7;
        cp16(st + row * (LDS_STRIDE * 4) + ch * 16,
             g_X + (size_t)(by * BM + row) * IN_F + k0 + ch * 8);
    }
    // B: 128 rows (out-features) x 64 halves -> 8 per thread
    #pragma unroll
    for (int it = 0; it < 8; it++) {
        int idx = tid + it * NTHREADS;
        int row = idx >> 3, ch = idx & 7;
        cp16(st + A_TILE_B + row * (LDS_STRIDE * 4) + ch * 16,
             g_W + (size_t)(bx * BN + row) * IN_F + k0 + ch * 8);
    }
}

__global__ __launch_bounds__(NTHREADS, 2)
void gemm_f16_kernel(const float* __restrict__ bmu,
                     const float* __restrict__ brho,
                     const float* __restrict__ beps,
                     float* __restrict__ C) {
    extern __shared__ char smem[];
    const uint32_t sbase = smem_u32(smem);
    const int tid = (int)threadIdx.x;
    const int wid = tid >> 5;          // 0..3
    const int lane = tid & 31;
    const int la = lane >> 2;          // groupID 0..7
    const int lb = lane & 3;           // threadID-in-group 0..3
    const int warpM = wid & 1;         // 2 warps along M (64 rows each)
    const int warpN = wid >> 1;        // 2 warps along N (64 cols each)
    const int bx = blockIdx.x;         // N tile
    const int by = blockIdx.y;         // M tile

    // Fused bias into smem: b = mu + softplus(rho)*eps (tid covers BN=128)
    float* sb = reinterpret_cast<float*>(smem + OFF_BIAS);
    {
        int col = bx * BN + tid;
        sb[tid] = fmaf(log1pf(__expf(brho[col])), beps[col], bmu[col]);
    }

    float d[4][8][4];
    #pragma unroll
    for (int mi = 0; mi < 4; mi++)
        #pragma unroll
        for (int ni = 0; ni < 8; ni++)
            #pragma unroll
            for (int j = 0; j < 4; j++) d[mi][ni][j] = 0.0f;

    // Prologue: preload groups 0,1 into stages 0,1
    load_stage(sbase, 0, 0, bx, by, tid);
    CP_COMMIT();
    load_stage(sbase, 1, 1, bx, by, tid);
    CP_COMMIT();

    for (int i = 0; i < NK; i++) {
        // 1) Retire group i (own copies); last iter: full drain.
        if (i < NK - 1) { CP_WAIT(1); } else { CP_WAIT(0); }
        // 2) Publish all threads' copies; WAR-protect stage (i+2)%3.
        __syncthreads();
        // 3) Issue next stage load early.
        if (i + 2 < NK) {
            load_stage(sbase, (i + 2) % STAGES, i + 2, bx, by, tid);
            CP_COMMIT();
        }

        // 4) Compute on stage i%3. Rows are 36 uint32 wide; data = 32 words
        //    (64 halves). Each uint32 = half-pair (k, k+1).
        const int stg = i % STAGES;
        const uint32_t* As = reinterpret_cast<const uint32_t*>(smem + stg * STAGE_B);
        const uint32_t* Bs = reinterpret_cast<const uint32_t*>(smem + stg * STAGE_B + A_TILE_B);

        #pragma unroll
        for (int s = 0; s < 4; s++) {          // k-steps of 16 halves
            const int ck = s * 8 + lb;         // uint32 (half-pair) index
            uint32_t a[4][4];
            #pragma unroll
            for (int mi = 0; mi < 4; mi++) {
                const int base = (warpM * 64 + mi * 16 + la) * LDS_STRIDE + ck;
                a[mi][0] = As[base];                          // row la,   k 2lb
                a[mi][1] = As[base + 8 * LDS_STRIDE];         // row la+8, k 2lb
                a[mi][2] = As[base + 4];                      // row la,   k 2lb+8
                a[mi][3] = As[base + 8 * LDS_STRIDE + 4];     // row la+8, k 2lb+8
            }
            #pragma unroll
            for (int ni = 0; ni < 8; ni++) {
                const int bbase = (warpN * 64 + ni * 8 + la) * LDS_STRIDE + ck;
                uint32_t b[2];
                b[0] = Bs[bbase];                             // n la, k 2lb
                b[1] = Bs[bbase + 4];                         // n la, k 2lb+8
                #pragma unroll
                for (int mi = 0; mi < 4; mi++)
                    mma_f16(d[mi][ni], a[mi], b);
            }
        }
    }

    // Epilogue: add bias, write float2 per fragment half
    #pragma unroll
    for (int mi = 0; mi < 4; mi++) {
        const int row0 = by * BM + warpM * 64 + mi * 16 + la;
        #pragma unroll
        for (int ni = 0; ni < 8; ni++) {
            const int cl = warpN * 64 + ni * 8 + 2 * lb;   // local col
            const int col = bx * BN + cl;
            float2 o0, o1;
            o0.x = d[mi][ni][0] + sb[cl];
            o0.y = d[mi][ni][1] + sb[cl + 1];
            o1.x = d[mi][ni][2] + sb[cl];
            o1.y = d[mi][ni][3] + sb[cl + 1];
            *reinterpret_cast<float2*>(C + (size_t)row0 * OUT_F + col)       = o0;
            *reinterpret_cast<float2*>(C + (size_t)(row0 + 8) * OUT_F + col) = o1;
        }
    }
}

// ---------------------------------------------------------------------------
// Inputs (metadata order):
//   0: x [T,I]  1: weight_mu [O,I]  2: weight_rho [O,I]
//   3: bias_mu [O]  4: bias_rho [O]  5: weight_eps [O,I]  6: bias_eps [O]
// ---------------------------------------------------------------------------
extern "C" void kernel_launch(void* const* d_in, const int* in_sizes, int n_in,
                              void* d_out, int out_size) {
    const float* x    = (const float*)d_in[0];
    const float* wmu  = (const float*)d_in[1];
    const float* wrho = (const float*)d_in[2];
    const float* bmu  = (const float*)d_in[3];
    const float* brho = (const float*)d_in[4];
    const float* weps = (const float*)d_in[5];
    const float* beps = (const float*)d_in[6];
    float* out = (float*)d_out;

    {
        int total4 = (OUT_F * IN_F) / 4;
        prep_w_kernel<<<total4 / 256, 256>>>(
            (const float4*)wmu, (const float4*)wrho, (const float4*)weps);
        prep_x_kernel<<<(TOKENS * IN_F / 4) / 256, 256>>>((const float4*)x);
    }

    cudaFuncSetAttribute(gemm_f16_kernel,
                         cudaFuncAttributeMaxDynamicSharedMemorySize, SMEM_TOTAL);
    dim3 grid(OUT_F / BN, TOKENS / BM);   // (32, 32)
    gemm_f16_kernel<<<grid, NTHREADS, SMEM_TOTAL>>>(bmu, brho, beps, out);
}